// round 7
// baseline (speedup 1.0000x reference)
#include <cuda_runtime.h>

#define L      8192
#define NPAIR  (L/2)          // 4096 packed (lo=i, hi=i+4096) pairs
#define KK     31
#define HALF   15
#define NT     256
#define CP     16             // output pairs per thread
#define WP     (CP + KK - 1)  // 46 window pairs
#define ULEN   (NPAIR + 2*HALF)             // 4126 logical pairs incl halos
#define PHYS64 (ULEN + (ULEN >> 4) + 2)     // padded u64 length
#define EPS    1e-6f

typedef unsigned long long u64;

// compile-time window offset: logical window index k -> offset from (base + 17*tid)
#define OFS(k) ((k) + ((k) >> 4))

// general physical index (seam/init paths only); logical pair i in [-15, NPAIR+15)
__device__ __forceinline__ int p64(int i) {
    int u = i + HALF;
    return u + (u >> 4);
}

__device__ __forceinline__ u64 pk2(float lo, float hi) {
    u64 r;
    asm("mov.b64 %0, {%1, %2};" : "=l"(r) : "f"(lo), "f"(hi));
    return r;
}
__device__ __forceinline__ void upk2(u64 v, float &lo, float &hi) {
    asm("mov.b64 {%0, %1}, %2;" : "=f"(lo), "=f"(hi) : "l"(v));
}
// d = a*b + d on packed f32x2 (sm_100+; PTX-only)
__device__ __forceinline__ void fma2(u64 &d, u64 a, u64 b) {
    asm("fma.rn.f32x2 %0, %1, %2, %0;" : "+l"(d) : "l"(a), "l"(b));
}

#define EPS2 0x358637BD358637BDULL   // (1e-6f, 1e-6f) packed

// 31-tap conv over packed pairs. base = buf + 17*tid (logical pair b-15).
// All shared offsets are compile-time immediates: zero address ALU.
__device__ __forceinline__ void conv_pairs(const u64* __restrict__ base,
                                           const u64* __restrict__ taps,
                                           u64 acc[CP]) {
    u64 r[WP];
    #pragma unroll
    for (int k = 0; k < 18; ++k)
        r[k] = base[OFS(k)];
    #pragma unroll
    for (int p = 0; p < CP; ++p) acc[p] = EPS2;     // "+EPS" folded into init
    #pragma unroll
    for (int j = 0; j < KK; ++j) {
        if (j + 18 < WP)
            r[j + 18] = base[OFS(j + 18)];           // prefetch ahead of use
        const u64 w = taps[j];                       // LDS.64 broadcast, pre-packed (w,w)
        #pragma unroll
        for (int p = 0; p < CP; ++p)
            fma2(acc[p], r[p + j], w);
    }
}

__global__ void __launch_bounds__(NT, 2)
drl_kernel(const float* __restrict__ m,
           const float* __restrict__ psf,
           const float* __restrict__ alpha,
           float* __restrict__ out,
           int nlayers) {
    extern __shared__ u64 smbuf[];
    u64* S = smbuf;                 // estimate pairs, padded + halos
    u64* T = smbuf + PHYS64;        // ratio pairs, padded + halos
    __shared__ u64 Wf[KK], Wr[KK];

    const int tid = threadIdx.x;
    const int row = blockIdx.x;

    if (tid < KK) {
        float w = psf[tid];
        float v = psf[KK - 1 - tid];
        Wf[tid] = pk2(w, w);
        Wr[tid] = pk2(v, v);
    }

    // init S (incl. halo pairs): pair i = (s[i], s[i+4096]); 0.5 inside, 0 outside
    for (int u = tid; u < ULEN; u += NT) {
        int i = u - HALF;
        float lo = (i >= 0)    ? 0.5f : 0.0f;
        float hi = (i < NPAIR) ? 0.5f : 0.0f;
        S[u + (u >> 4)] = pk2(lo, hi);
    }

    const int b = tid * CP;
    u64* const Sb = S + 17 * tid;   // base at logical pair b-15
    u64* const Tb = T + 17 * tid;

    // x row pre-paired into 16 persistent registers (one coalesced HBM read)
    u64 xr[CP];
    {
        const float* mrow = m + (size_t)row * L;
        const float4* ma = (const float4*)(mrow + b);
        const float4* mb = (const float4*)(mrow + b + NPAIR);
        #pragma unroll
        for (int q = 0; q < 4; ++q) {
            float4 av = ma[q], bv = mb[q];
            xr[q * 4 + 0] = pk2(av.x, bv.x);
            xr[q * 4 + 1] = pk2(av.y, bv.y);
            xr[q * 4 + 2] = pk2(av.z, bv.z);
            xr[q * 4 + 3] = pk2(av.w, bv.w);
        }
    }
    __syncthreads();

    for (int layer = 0; layer < nlayers; ++layer) {
        const float a = alpha[layer];

        // ---- pass 1: ratio = x / (conv(S,w)+EPS) -> T (+ seam halos) ----
        {
            u64 acc[CP];
            conv_pairs(Sb, Wf, acc);
            #pragma unroll
            for (int p = 0; p < CP; ++p) {
                float sa, sb, xa, xb;
                upk2(acc[p], sa, sb);
                upk2(xr[p], xa, xb);
                Tb[OFS(p + HALF)] = pk2(__fdividef(xa, sa), __fdividef(xb, sb));
            }
            // seam halos: right halo from thread 0's hi lanes, left from last thread's lo lanes
            if (tid == 0) {
                #pragma unroll
                for (int p = 0; p < HALF; ++p) {
                    float lo, hi; upk2(T[p64(p)], lo, hi);
                    T[p64(NPAIR + p)] = pk2(hi, 0.0f);
                }
            }
            if (tid == NT - 1) {
                #pragma unroll
                for (int p = 1; p <= HALF; ++p) {
                    float lo, hi; upk2(T[p64(b + p)], lo, hi);
                    T[p64(b + p - NPAIR)] = pk2(0.0f, lo);
                }
            }
        }
        __syncthreads();

        // ---- pass 2: corr = max(conv(T,wflip)+EPS, EPS); S = max(S*corr^a, EPS) ----
        {
            u64 acc[CP];
            conv_pairs(Tb, Wr, acc);
            #pragma unroll
            for (int p = 0; p < CP; ++p) {
                float ca, cb;
                upk2(acc[p], ca, cb);
                ca = fmaxf(ca, EPS);
                cb = fmaxf(cb, EPS);
                if (a != 1.0f) {               // warp-uniform; skipped for alpha==1
                    ca = __powf(ca, a);
                    cb = __powf(cb, a);
                }
                float so, sh;
                upk2(Sb[OFS(p + HALF)], so, sh);
                so = fmaxf(so * ca, EPS);
                sh = fmaxf(sh * cb, EPS);
                Sb[OFS(p + HALF)] = pk2(so, sh);
            }
            if (tid == 0) {
                #pragma unroll
                for (int p = 0; p < HALF; ++p) {
                    float lo, hi; upk2(S[p64(p)], lo, hi);
                    S[p64(NPAIR + p)] = pk2(hi, 0.0f);
                }
            }
            if (tid == NT - 1) {
                #pragma unroll
                for (int p = 1; p <= HALF; ++p) {
                    float lo, hi; upk2(S[p64(b + p)], lo, hi);
                    S[p64(b + p - NPAIR)] = pk2(0.0f, lo);
                }
            }
        }
        __syncthreads();
    }

    // coalesced output store: unpack pairs into the two half-row segments
    {
        float* orow = out + (size_t)row * L;
        #pragma unroll
        for (int q = 0; q < 4; ++q) {
            float4 va, vb;
            float lo, hi;
            upk2(Sb[OFS(q * 4 + 0 + HALF)], lo, hi); va.x = lo; vb.x = hi;
            upk2(Sb[OFS(q * 4 + 1 + HALF)], lo, hi); va.y = lo; vb.y = hi;
            upk2(Sb[OFS(q * 4 + 2 + HALF)], lo, hi); va.z = lo; vb.z = hi;
            upk2(Sb[OFS(q * 4 + 3 + HALF)], lo, hi); va.w = lo; vb.w = hi;
            ((float4*)(orow + b))[q] = va;
            ((float4*)(orow + b + NPAIR))[q] = vb;
        }
    }
}

extern "C" void kernel_launch(void* const* d_in, const int* in_sizes, int n_in,
                              void* d_out, int out_size) {
    const float* m     = (const float*)d_in[0];
    const float* psf   = (const float*)d_in[1];
    const float* alpha = (const float*)d_in[2];
    float* out = (float*)d_out;

    const int nlayers = in_sizes[2];
    const int B = in_sizes[0] / L;
    const int smem_bytes = 2 * PHYS64 * (int)sizeof(u64);

    cudaFuncSetAttribute(drl_kernel, cudaFuncAttributeMaxDynamicSharedMemorySize, smem_bytes);
    drl_kernel<<<B, NT, smem_bytes>>>(m, psf, alpha, out, nlayers);
}